// round 13
// baseline (speedup 1.0000x reference)
#include <cuda_runtime.h>
#include <cstdint>

#define LN_ZERO (-100000000000.0f)

// ---------------------------------------------------------------------------
// L2 cache-policy helpers (sm_80+): evict_last keeps the RMW targets resident.
// ---------------------------------------------------------------------------
__device__ __forceinline__ uint64_t mk_evict_last() {
    uint64_t p;
    asm("createpolicy.fractional.L2::evict_last.b64 %0, 1.0;" : "=l"(p));
    return p;
}
__device__ __forceinline__ void red_add_v2_el(float* p, float a, float b, uint64_t pol) {
    asm volatile("red.global.add.L2::cache_hint.v2.f32 [%0], {%1, %2}, %3;"
                 :: "l"(p), "f"(a), "f"(b), "l"(pol) : "memory");
}
__device__ __forceinline__ void red_add_v4_el(float* p, float a, float b, float c,
                                              float d, uint64_t pol) {
    asm volatile("red.global.add.L2::cache_hint.v4.f32 [%0], {%1, %2, %3, %4}, %5;"
                 :: "l"(p), "f"(a), "f"(b), "f"(c), "f"(d), "l"(pol) : "memory");
}
__device__ __forceinline__ void st_v4_el(float4* p, float4 v, uint64_t pol) {
    asm volatile("st.global.L2::cache_hint.v4.f32 [%0], {%1, %2, %3, %4}, %5;"
                 :: "l"(p), "f"(v.x), "f"(v.y), "f"(v.z), "f"(v.w), "l"(pol) : "memory");
}
__device__ __forceinline__ float2 ld_v2_el(const float2* p, uint64_t pol) {
    float2 r;
    asm volatile("ld.global.L2::cache_hint.v2.f32 {%0, %1}, [%2], %3;"
                 : "=f"(r.x), "=f"(r.y) : "l"(p), "l"(pol));
    return r;
}
__device__ __forceinline__ float4 ld_v4_el(const float4* p, uint64_t pol) {
    float4 r;
    asm volatile("ld.global.L2::cache_hint.v4.f32 {%0, %1, %2, %3}, [%4], %5;"
                 : "=f"(r.x), "=f"(r.y), "=f"(r.z), "=f"(r.w) : "l"(p), "l"(pol));
    return r;
}
__device__ __forceinline__ void prefetch_l2(const void* p) {
    asm volatile("prefetch.global.L2 [%0];" :: "l"(p));
}

// ---------------------------------------------------------------------------
// Kernel 1: zero the var-belief accumulator region, pinned evict_last.
// ---------------------------------------------------------------------------
__global__ void __launch_bounds__(256) k_zero_var(float4* __restrict__ out, int n4) {
    cudaTriggerProgrammaticLaunchCompletion();
    int i = blockIdx.x * blockDim.x + threadIdx.x;
    if (i < n4) {
        uint64_t pol = mk_evict_last();
        st_v4_el(out + i, make_float4(0.f, 0.f, 0.f, 0.f), pol);
    }
}

// ---------------------------------------------------------------------------
// Kernel 2 (phase A, fused): block-partitioned independent work.
//   [0, B_acc):       var segment-sum (2 edges/thread, v2 red, evict_last)
//   [B_acc, +B_pot):  potentials -> factor output region copy (evict_last st)
// ---------------------------------------------------------------------------
__global__ void __launch_bounds__(256) k_phaseA(
        const float* __restrict__ msg,
        const int* __restrict__ var_idx,
        float* __restrict__ out_var, int E,
        const float4* __restrict__ pot4,
        float4* __restrict__ out_factor4, int F4,
        int B_acc) {
    cudaTriggerProgrammaticLaunchCompletion();
    int b = blockIdx.x;
    int tid = threadIdx.x;

    if (b < B_acc) {
        uint64_t pol = mk_evict_last();
        int i = b * 256 + tid;
        int e0 = 2 * i;
        if (e0 + 1 < E) {
            float4 m = __ldcs((const float4*)msg + i);
            int2 vv = __ldcs((const int2*)var_idx + i);
            cudaGridDependencySynchronize();            // out_var must be zeroed
            red_add_v2_el(out_var + 2 * vv.x, m.x, m.y, pol);
            red_add_v2_el(out_var + 2 * vv.y, m.z, m.w, pol);
        } else if (e0 < E) {
            float2 m = __ldcs((const float2*)msg + e0);
            int v = __ldcs(var_idx + e0);
            cudaGridDependencySynchronize();
            red_add_v2_el(out_var + 2 * v, m.x, m.y, pol);
        } else {
            cudaGridDependencySynchronize();
        }
    } else {
        // pot copy fully overwrites its range — independent of the zero kernel.
        uint64_t pol = mk_evict_last();
        int i = (b - B_acc) * 256 + tid;
        int j0 = 2 * i;
        if (j0 + 1 < F4) {
            st_v4_el(out_factor4 + j0,     __ldcs(pot4 + j0), pol);
            st_v4_el(out_factor4 + j0 + 1, __ldcs(pot4 + j0 + 1), pol);
        } else if (j0 < F4) {
            st_v4_el(out_factor4 + j0, __ldcs(pot4 + j0), pol);
        }
    }
}

// ---------------------------------------------------------------------------
// Kernel 3: var mask + clamp in place (evict_last ld/st — gathered next).
// ---------------------------------------------------------------------------
__global__ void __launch_bounds__(256) k_var_mask(float4* __restrict__ var,
                                                  const int4* __restrict__ mask,
                                                  int nPairs) {
    cudaTriggerProgrammaticLaunchCompletion();
    int i = blockIdx.x * blockDim.x + threadIdx.x;
    if (i >= nPairs) {
        cudaGridDependencySynchronize();
        return;
    }
    uint64_t pol = mk_evict_last();
    int4 m = __ldcs(mask + i);              // independent stream — preamble
    cudaGridDependencySynchronize();        // wait for phaseA's REDs
    float4 v = ld_v4_el(var + i, pol);
    v.x = m.x ? LN_ZERO : fmaxf(v.x, LN_ZERO);
    v.y = m.y ? LN_ZERO : fmaxf(v.y, LN_ZERO);
    v.z = m.z ? LN_ZERO : fmaxf(v.z, LN_ZERO);
    v.w = m.w ? LN_ZERO : fmaxf(v.w, LN_ZERO);
    st_v4_el(var + i, v, pol);
}

// ---------------------------------------------------------------------------
// Kernel 4: per edge: v2f = vb[var] - msg, mask+clamp, permute (sidx element 1,
// bit 1), v4 red (evict_last) into factor accumulator. 2 edges per thread.
// Late blocks additionally prefetch fp_mask into L2 (normal priority) using
// this kernel's idle DRAM bandwidth, so k_factor_mask's mask reads hit L2.
// ---------------------------------------------------------------------------
__global__ void __launch_bounds__(256) k_factor_accum(
        const float4* __restrict__ msg2,
        const int2* __restrict__ fac_idx2,
        const int2* __restrict__ var_idx2,
        const int4* __restrict__ v2f_mask2,
        const int* __restrict__ sidx,
        const float2* __restrict__ var_beliefs,
        const float2* __restrict__ msg,
        const int* __restrict__ fac_idx,
        const int* __restrict__ var_idx,
        const int2* __restrict__ v2f_mask,
        float* __restrict__ out_factor, int E,
        const char* __restrict__ pref_base, int pref_lines, int pref_block0) {
    cudaTriggerProgrammaticLaunchCompletion();

    // L2 prefetch of fp_mask from the last blocks (independent input data).
    if ((int)blockIdx.x >= pref_block0) {
        int line = (blockIdx.x - pref_block0) * 256 + threadIdx.x;
        if (line < pref_lines) prefetch_l2(pref_base + (size_t)line * 128);
    }

    int i = blockIdx.x * blockDim.x + threadIdx.x;
    int e0 = 2 * i;
    if (e0 + 1 < E) {
        uint64_t pol = mk_evict_last();
        float4 m  = __ldcs(msg2 + i);
        int2   ff = __ldcs(fac_idx2 + i);
        int2   vv = __ldcs(var_idx2 + i);
        int4   mk = __ldcs(v2f_mask2 + i);
        int    s0 = __ldcs(sidx + 8 * i + 1);
        int    s1 = __ldcs(sidx + 8 * i + 5);
        cudaGridDependencySynchronize();    // var_beliefs final; out_factor potted
        float2 vb0 = ld_v2_el(var_beliefs + vv.x, pol);
        float2 vb1 = ld_v2_el(var_beliefs + vv.y, pol);

        float a = mk.x ? LN_ZERO : fmaxf(vb0.x - m.x, LN_ZERO);
        float b = mk.y ? LN_ZERO : fmaxf(vb0.y - m.y, LN_ZERO);
        bool p0 = (s0 & 2) != 0;
        red_add_v4_el(out_factor + 4 * ff.x, a, p0 ? b : a, p0 ? a : b, b, pol);

        float c = mk.z ? LN_ZERO : fmaxf(vb1.x - m.z, LN_ZERO);
        float d = mk.w ? LN_ZERO : fmaxf(vb1.y - m.w, LN_ZERO);
        bool p1 = (s1 & 2) != 0;
        red_add_v4_el(out_factor + 4 * ff.y, c, p1 ? d : c, p1 ? c : d, d, pol);
    } else if (e0 < E) {
        uint64_t pol = mk_evict_last();
        float2 m  = __ldcs(msg + e0);
        int    f  = __ldcs(fac_idx + e0);
        int    v  = __ldcs(var_idx + e0);
        int2   mk = __ldcs(v2f_mask + e0);
        int    s  = __ldcs(sidx + 4 * e0 + 1);
        cudaGridDependencySynchronize();
        float2 vb = ld_v2_el(var_beliefs + v, pol);
        float a = mk.x ? LN_ZERO : fmaxf(vb.x - m.x, LN_ZERO);
        float b = mk.y ? LN_ZERO : fmaxf(vb.y - m.y, LN_ZERO);
        bool p = (s & 2) != 0;
        red_add_v4_el(out_factor + 4 * f, a, p ? b : a, p ? a : b, b, pol);
    } else {
        cudaGridDependencySynchronize();
    }
}

// ---------------------------------------------------------------------------
// Kernel 5: factor mask + clamp in place, 2 factors per thread.
// Mask reads should now mostly hit L2 (prefetched); fb reads hit pinned lines.
// ---------------------------------------------------------------------------
__global__ void __launch_bounds__(256) k_factor_mask(float4* __restrict__ fb,
                                                     const int4* __restrict__ mask,
                                                     int nF) {
    int i = blockIdx.x * blockDim.x + threadIdx.x;
    int j0 = 2 * i;
    if (j0 + 1 < nF) {
        int4 m0 = __ldcs(mask + j0);
        int4 m1 = __ldcs(mask + j0 + 1);
        cudaGridDependencySynchronize();    // all REDs into out_factor done
        float4 v0 = fb[j0];
        float4 v1 = fb[j0 + 1];
        v0.x = m0.x ? LN_ZERO : fmaxf(v0.x, LN_ZERO);
        v0.y = m0.y ? LN_ZERO : fmaxf(v0.y, LN_ZERO);
        v0.z = m0.z ? LN_ZERO : fmaxf(v0.z, LN_ZERO);
        v0.w = m0.w ? LN_ZERO : fmaxf(v0.w, LN_ZERO);
        v1.x = m1.x ? LN_ZERO : fmaxf(v1.x, LN_ZERO);
        v1.y = m1.y ? LN_ZERO : fmaxf(v1.y, LN_ZERO);
        v1.z = m1.z ? LN_ZERO : fmaxf(v1.z, LN_ZERO);
        v1.w = m1.w ? LN_ZERO : fmaxf(v1.w, LN_ZERO);
        __stcs(fb + j0, v0);
        __stcs(fb + j0 + 1, v1);
    } else if (j0 < nF) {
        int4 m0 = __ldcs(mask + j0);
        cudaGridDependencySynchronize();
        float4 v0 = fb[j0];
        v0.x = m0.x ? LN_ZERO : fmaxf(v0.x, LN_ZERO);
        v0.y = m0.y ? LN_ZERO : fmaxf(v0.y, LN_ZERO);
        v0.z = m0.z ? LN_ZERO : fmaxf(v0.z, LN_ZERO);
        v0.w = m0.w ? LN_ZERO : fmaxf(v0.w, LN_ZERO);
        __stcs(fb + j0, v0);
    } else {
        cudaGridDependencySynchronize();
    }
}

// ---------------------------------------------------------------------------
// Host: launch chain with Programmatic Dependent Launch.
// ---------------------------------------------------------------------------
template <typename... Args>
static void launch_pdl(void (*kern)(Args...), int grid, int block, Args... args) {
    cudaLaunchConfig_t cfg = {};
    cfg.gridDim = dim3((unsigned)grid, 1, 1);
    cfg.blockDim = dim3((unsigned)block, 1, 1);
    cfg.dynamicSmemBytes = 0;
    cfg.stream = 0;
    cudaLaunchAttribute attr[1];
    attr[0].id = cudaLaunchAttributeProgrammaticStreamSerialization;
    attr[0].val.programmaticStreamSerializationAllowed = 1;
    cfg.attrs = attr;
    cfg.numAttrs = 1;
    cudaLaunchKernelEx(&cfg, kern, args...);
}

extern "C" void kernel_launch(void* const* d_in, const int* in_sizes, int n_in,
                              void* d_out, int out_size) {
    const float* msg      = (const float*)d_in[0];
    const float* pot      = (const float*)d_in[1];
    const int*   edge_idx = (const int*)d_in[2];
    const int*   fp_mask  = (const int*)d_in[3];
    const int*   v2f_mask = (const int*)d_in[4];
    const int*   vb_mask  = (const int*)d_in[5];
    const int*   sidx     = (const int*)d_in[6];

    const int E = in_sizes[0] / 2;
    const int F = in_sizes[1] / 4;
    const int V = in_sizes[5] / 2;

    const int* fac_idx = edge_idx;
    const int* var_idx = edge_idx + E;

    float* out_var    = (float*)d_out;            // [V,2]
    float* out_factor = out_var + (size_t)2 * V;  // [F,2,2]

    const int T = 256;

    // 1) zero var accumulator region (pinned)
    int nv4 = (2 * V) / 4;
    k_zero_var<<<(nv4 + T - 1) / T, T>>>((float4*)d_out, nv4);

    // 2) phase A: var segment-sum + potentials copy (fused) — PDL after zero
    int nPairsE = (E + 1) / 2;
    int B_acc  = (nPairsE + T - 1) / T;
    int nPotTh = (F + 1) / 2;
    int B_pot  = (nPotTh + T - 1) / T;
    launch_pdl(k_phaseA, B_acc + B_pot, T,
               msg, var_idx, out_var, E,
               (const float4*)pot, (float4*)out_factor, F, B_acc);

    // 3) var mask + clamp — PDL after phaseA
    int nPairsV = V / 2;
    launch_pdl(k_var_mask, (nPairsV + T - 1) / T, T,
               (float4*)out_var, (const int4*)vb_mask, nPairsV);

    // 4) edge pass — PDL after var_mask; late blocks prefetch fp_mask to L2
    int grid4 = (nPairsE + T - 1) / T;
    long long maskBytes = (long long)F * 16;           // F * 4 ints * 4B
    int pref_lines = (int)((maskBytes + 127) / 128);
    int pref_blocks = (pref_lines + T - 1) / T;
    int pref_block0 = grid4 > pref_blocks ? grid4 - pref_blocks : 0;
    launch_pdl(k_factor_accum, grid4, T,
               (const float4*)msg, (const int2*)fac_idx, (const int2*)var_idx,
               (const int4*)v2f_mask, sidx, (const float2*)out_var,
               (const float2*)msg, fac_idx, var_idx, (const int2*)v2f_mask,
               out_factor, E,
               (const char*)fp_mask, pref_lines, pref_block0);

    // 5) factor mask + clamp — PDL after factor_accum
    int nPairsF = (F + 1) / 2;
    launch_pdl(k_factor_mask, (nPairsF + T - 1) / T, T,
               (float4*)out_factor, (const int4*)fp_mask, F);
}

// round 14
// speedup vs baseline: 1.0520x; 1.0520x over previous
#include <cuda_runtime.h>
#include <cstdint>

#define LN_ZERO (-100000000000.0f)

// ---------------------------------------------------------------------------
// L2 cache-policy helpers (sm_80+): evict_last keeps the RMW targets resident.
// ---------------------------------------------------------------------------
__device__ __forceinline__ uint64_t mk_evict_last() {
    uint64_t p;
    asm("createpolicy.fractional.L2::evict_last.b64 %0, 1.0;" : "=l"(p));
    return p;
}
__device__ __forceinline__ void red_add_v2_el(float* p, float a, float b, uint64_t pol) {
    asm volatile("red.global.add.L2::cache_hint.v2.f32 [%0], {%1, %2}, %3;"
                 :: "l"(p), "f"(a), "f"(b), "l"(pol) : "memory");
}
__device__ __forceinline__ void red_add_v4_el(float* p, float a, float b, float c,
                                              float d, uint64_t pol) {
    asm volatile("red.global.add.L2::cache_hint.v4.f32 [%0], {%1, %2, %3, %4}, %5;"
                 :: "l"(p), "f"(a), "f"(b), "f"(c), "f"(d), "l"(pol) : "memory");
}
__device__ __forceinline__ void st_v4_el(float4* p, float4 v, uint64_t pol) {
    asm volatile("st.global.L2::cache_hint.v4.f32 [%0], {%1, %2, %3, %4}, %5;"
                 :: "l"(p), "f"(v.x), "f"(v.y), "f"(v.z), "f"(v.w), "l"(pol) : "memory");
}
__device__ __forceinline__ float2 ld_v2_el(const float2* p, uint64_t pol) {
    float2 r;
    asm volatile("ld.global.L2::cache_hint.v2.f32 {%0, %1}, [%2], %3;"
                 : "=f"(r.x), "=f"(r.y) : "l"(p), "l"(pol));
    return r;
}
__device__ __forceinline__ float4 ld_v4_el(const float4* p, uint64_t pol) {
    float4 r;
    asm volatile("ld.global.L2::cache_hint.v4.f32 {%0, %1, %2, %3}, [%4], %5;"
                 : "=f"(r.x), "=f"(r.y), "=f"(r.z), "=f"(r.w) : "l"(p), "l"(pol));
    return r;
}

// ---------------------------------------------------------------------------
// Kernel 1: zero the var-belief accumulator region, pinned evict_last.
// Primary for phaseA (PDL).
// ---------------------------------------------------------------------------
__global__ void __launch_bounds__(256) k_zero_var(float4* __restrict__ out, int n4) {
    cudaTriggerProgrammaticLaunchCompletion();
    int i = blockIdx.x * blockDim.x + threadIdx.x;
    if (i < n4) {
        uint64_t pol = mk_evict_last();
        st_v4_el(out + i, make_float4(0.f, 0.f, 0.f, 0.f), pol);
    }
}

// ---------------------------------------------------------------------------
// Kernel 2 (phase A, fused): block-partitioned independent work.
//   [0, B_acc):       var segment-sum (2 edges/thread, v2 red, evict_last)
//   [B_acc, +B_pot):  potentials -> factor output region copy (evict_last st)
// PDL secondary of k_zero_var (REDs must see zeroed out_var) and primary for
// k_var_mask. Independent stream loads run before the dependency sync.
// ---------------------------------------------------------------------------
__global__ void __launch_bounds__(256) k_phaseA(
        const float* __restrict__ msg,
        const int* __restrict__ var_idx,
        float* __restrict__ out_var, int E,
        const float4* __restrict__ pot4,
        float4* __restrict__ out_factor4, int F4,
        int B_acc) {
    cudaTriggerProgrammaticLaunchCompletion();
    int b = blockIdx.x;
    int tid = threadIdx.x;

    if (b < B_acc) {
        uint64_t pol = mk_evict_last();
        int i = b * 256 + tid;
        int e0 = 2 * i;
        if (e0 + 1 < E) {
            float4 m = __ldcs((const float4*)msg + i);
            int2 vv = __ldcs((const int2*)var_idx + i);
            cudaGridDependencySynchronize();            // out_var must be zeroed
            red_add_v2_el(out_var + 2 * vv.x, m.x, m.y, pol);
            red_add_v2_el(out_var + 2 * vv.y, m.z, m.w, pol);
        } else if (e0 < E) {
            float2 m = __ldcs((const float2*)msg + e0);
            int v = __ldcs(var_idx + e0);
            cudaGridDependencySynchronize();
            red_add_v2_el(out_var + 2 * v, m.x, m.y, pol);
        } else {
            cudaGridDependencySynchronize();
        }
    } else {
        // pot copy is independent of the zero kernel (full overwrite) — no sync
        // needed for correctness of these stores.
        uint64_t pol = mk_evict_last();
        int i = (b - B_acc) * 256 + tid;
        int j0 = 2 * i;
        if (j0 + 1 < F4) {
            st_v4_el(out_factor4 + j0,     __ldcs(pot4 + j0), pol);
            st_v4_el(out_factor4 + j0 + 1, __ldcs(pot4 + j0 + 1), pol);
        } else if (j0 < F4) {
            st_v4_el(out_factor4 + j0, __ldcs(pot4 + j0), pol);
        }
    }
}

// ---------------------------------------------------------------------------
// Kernel 3: var mask + clamp in place (evict_last ld/st — gathered next).
// PDL secondary of phaseA; primary for factor_accum. Mask stream (independent)
// loads before the sync; the var read (dependent) after.
// ---------------------------------------------------------------------------
__global__ void __launch_bounds__(256) k_var_mask(float4* __restrict__ var,
                                                  const int4* __restrict__ mask,
                                                  int nPairs) {
    cudaTriggerProgrammaticLaunchCompletion();
    int i = blockIdx.x * blockDim.x + threadIdx.x;
    if (i >= nPairs) {
        cudaGridDependencySynchronize();
        return;
    }
    uint64_t pol = mk_evict_last();
    int4 m = __ldcs(mask + i);              // independent stream — preamble
    cudaGridDependencySynchronize();        // wait for phaseA's REDs
    float4 v = ld_v4_el(var + i, pol);
    v.x = m.x ? LN_ZERO : fmaxf(v.x, LN_ZERO);
    v.y = m.y ? LN_ZERO : fmaxf(v.y, LN_ZERO);
    v.z = m.z ? LN_ZERO : fmaxf(v.z, LN_ZERO);
    v.w = m.w ? LN_ZERO : fmaxf(v.w, LN_ZERO);
    st_v4_el(var + i, v, pol);
}

// ---------------------------------------------------------------------------
// Kernel 4: per edge: v2f = vb[var] - msg, mask+clamp, permute (sidx element 1,
// bit 1), v4 red (evict_last) into factor accumulator. 2 edges per thread.
// PDL secondary of var_mask; primary for factor_mask. All six independent
// stream loads run before the sync; vb gather + REDs after.
// ---------------------------------------------------------------------------
__global__ void __launch_bounds__(256) k_factor_accum(
        const float4* __restrict__ msg2,
        const int2* __restrict__ fac_idx2,
        const int2* __restrict__ var_idx2,
        const int4* __restrict__ v2f_mask2,
        const int* __restrict__ sidx,
        const float2* __restrict__ var_beliefs,
        const float2* __restrict__ msg,
        const int* __restrict__ fac_idx,
        const int* __restrict__ var_idx,
        const int2* __restrict__ v2f_mask,
        float* __restrict__ out_factor, int E) {
    cudaTriggerProgrammaticLaunchCompletion();
    int i = blockIdx.x * blockDim.x + threadIdx.x;
    int e0 = 2 * i;
    if (e0 + 1 < E) {
        uint64_t pol = mk_evict_last();
        float4 m  = __ldcs(msg2 + i);
        int2   ff = __ldcs(fac_idx2 + i);
        int2   vv = __ldcs(var_idx2 + i);
        int4   mk = __ldcs(v2f_mask2 + i);
        int    s0 = __ldcs(sidx + 8 * i + 1);
        int    s1 = __ldcs(sidx + 8 * i + 5);
        cudaGridDependencySynchronize();    // var_beliefs final; out_factor potted
        float2 vb0 = ld_v2_el(var_beliefs + vv.x, pol);
        float2 vb1 = ld_v2_el(var_beliefs + vv.y, pol);

        float a = mk.x ? LN_ZERO : fmaxf(vb0.x - m.x, LN_ZERO);
        float b = mk.y ? LN_ZERO : fmaxf(vb0.y - m.y, LN_ZERO);
        bool p0 = (s0 & 2) != 0;
        red_add_v4_el(out_factor + 4 * ff.x, a, p0 ? b : a, p0 ? a : b, b, pol);

        float c = mk.z ? LN_ZERO : fmaxf(vb1.x - m.z, LN_ZERO);
        float d = mk.w ? LN_ZERO : fmaxf(vb1.y - m.w, LN_ZERO);
        bool p1 = (s1 & 2) != 0;
        red_add_v4_el(out_factor + 4 * ff.y, c, p1 ? d : c, p1 ? c : d, d, pol);
    } else if (e0 < E) {
        uint64_t pol = mk_evict_last();
        float2 m  = __ldcs(msg + e0);
        int    f  = __ldcs(fac_idx + e0);
        int    v  = __ldcs(var_idx + e0);
        int2   mk = __ldcs(v2f_mask + e0);
        int    s  = __ldcs(sidx + 4 * e0 + 1);
        cudaGridDependencySynchronize();
        float2 vb = ld_v2_el(var_beliefs + v, pol);
        float a = mk.x ? LN_ZERO : fmaxf(vb.x - m.x, LN_ZERO);
        float b = mk.y ? LN_ZERO : fmaxf(vb.y - m.y, LN_ZERO);
        bool p = (s & 2) != 0;
        red_add_v4_el(out_factor + 4 * f, a, p ? b : a, p ? a : b, b, pol);
    } else {
        cudaGridDependencySynchronize();
    }
}

// ---------------------------------------------------------------------------
// Kernel 5: factor mask + clamp in place, 2 factors per thread.
// PDL secondary of factor_accum. Mask stream preloads before sync; fb reads
// (dependent, mostly L2 hits) after. Final stores evict-first.
// ---------------------------------------------------------------------------
__global__ void __launch_bounds__(256) k_factor_mask(float4* __restrict__ fb,
                                                     const int4* __restrict__ mask,
                                                     int nF) {
    int i = blockIdx.x * blockDim.x + threadIdx.x;
    int j0 = 2 * i;
    if (j0 + 1 < nF) {
        int4 m0 = __ldcs(mask + j0);
        int4 m1 = __ldcs(mask + j0 + 1);
        cudaGridDependencySynchronize();    // all REDs into out_factor done
        float4 v0 = fb[j0];
        float4 v1 = fb[j0 + 1];
        v0.x = m0.x ? LN_ZERO : fmaxf(v0.x, LN_ZERO);
        v0.y = m0.y ? LN_ZERO : fmaxf(v0.y, LN_ZERO);
        v0.z = m0.z ? LN_ZERO : fmaxf(v0.z, LN_ZERO);
        v0.w = m0.w ? LN_ZERO : fmaxf(v0.w, LN_ZERO);
        v1.x = m1.x ? LN_ZERO : fmaxf(v1.x, LN_ZERO);
        v1.y = m1.y ? LN_ZERO : fmaxf(v1.y, LN_ZERO);
        v1.z = m1.z ? LN_ZERO : fmaxf(v1.z, LN_ZERO);
        v1.w = m1.w ? LN_ZERO : fmaxf(v1.w, LN_ZERO);
        __stcs(fb + j0, v0);
        __stcs(fb + j0 + 1, v1);
    } else if (j0 < nF) {
        int4 m0 = __ldcs(mask + j0);
        cudaGridDependencySynchronize();
        float4 v0 = fb[j0];
        v0.x = m0.x ? LN_ZERO : fmaxf(v0.x, LN_ZERO);
        v0.y = m0.y ? LN_ZERO : fmaxf(v0.y, LN_ZERO);
        v0.z = m0.z ? LN_ZERO : fmaxf(v0.z, LN_ZERO);
        v0.w = m0.w ? LN_ZERO : fmaxf(v0.w, LN_ZERO);
        __stcs(fb + j0, v0);
    } else {
        cudaGridDependencySynchronize();
    }
}

// ---------------------------------------------------------------------------
// Host: launch chain with Programmatic Dependent Launch on each dependent
// kernel so successor CTAs launch during the predecessor's last wave.
// ---------------------------------------------------------------------------
template <typename... Args>
static void launch_pdl(void (*kern)(Args...), int grid, int block, Args... args) {
    cudaLaunchConfig_t cfg = {};
    cfg.gridDim = dim3((unsigned)grid, 1, 1);
    cfg.blockDim = dim3((unsigned)block, 1, 1);
    cfg.dynamicSmemBytes = 0;
    cfg.stream = 0;
    cudaLaunchAttribute attr[1];
    attr[0].id = cudaLaunchAttributeProgrammaticStreamSerialization;
    attr[0].val.programmaticStreamSerializationAllowed = 1;
    cfg.attrs = attr;
    cfg.numAttrs = 1;
    cudaLaunchKernelEx(&cfg, kern, args...);
}

extern "C" void kernel_launch(void* const* d_in, const int* in_sizes, int n_in,
                              void* d_out, int out_size) {
    const float* msg      = (const float*)d_in[0];
    const float* pot      = (const float*)d_in[1];
    const int*   edge_idx = (const int*)d_in[2];
    const int*   fp_mask  = (const int*)d_in[3];
    const int*   v2f_mask = (const int*)d_in[4];
    const int*   vb_mask  = (const int*)d_in[5];
    const int*   sidx     = (const int*)d_in[6];

    const int E = in_sizes[0] / 2;
    const int F = in_sizes[1] / 4;
    const int V = in_sizes[5] / 2;

    const int* fac_idx = edge_idx;
    const int* var_idx = edge_idx + E;

    float* out_var    = (float*)d_out;            // [V,2]
    float* out_factor = out_var + (size_t)2 * V;  // [F,2,2]

    const int T = 256;

    // 1) zero var accumulator region (pinned) — plain launch
    int nv4 = (2 * V) / 4;
    k_zero_var<<<(nv4 + T - 1) / T, T>>>((float4*)d_out, nv4);

    // 2) phase A: var segment-sum + potentials copy (fused) — PDL after zero
    int nPairsE = (E + 1) / 2;
    int B_acc  = (nPairsE + T - 1) / T;
    int nPotTh = (F + 1) / 2;
    int B_pot  = (nPotTh + T - 1) / T;
    launch_pdl(k_phaseA, B_acc + B_pot, T,
               msg, var_idx, out_var, E,
               (const float4*)pot, (float4*)out_factor, F, B_acc);

    // 3) var mask + clamp — PDL after phaseA
    int nPairsV = V / 2;
    launch_pdl(k_var_mask, (nPairsV + T - 1) / T, T,
               (float4*)out_var, (const int4*)vb_mask, nPairsV);

    // 4) edge pass: v2f + permute + factor segment-sum — PDL after var_mask
    launch_pdl(k_factor_accum, (nPairsE + T - 1) / T, T,
               (const float4*)msg, (const int2*)fac_idx, (const int2*)var_idx,
               (const int4*)v2f_mask, sidx, (const float2*)out_var,
               (const float2*)msg, fac_idx, var_idx, (const int2*)v2f_mask,
               out_factor, E);

    // 5) factor mask + clamp — PDL after factor_accum
    int nPairsF = (F + 1) / 2;
    launch_pdl(k_factor_mask, (nPairsF + T - 1) / T, T,
               (float4*)out_factor, (const int4*)fp_mask, F);
}

// round 15
// speedup vs baseline: 1.0535x; 1.0014x over previous
#include <cuda_runtime.h>
#include <cstdint>

#define LN_ZERO (-100000000000.0f)

// ---------------------------------------------------------------------------
// L2 cache-policy helpers (sm_80+): evict_last keeps the RMW targets resident.
// ---------------------------------------------------------------------------
__device__ __forceinline__ uint64_t mk_evict_last() {
    uint64_t p;
    asm("createpolicy.fractional.L2::evict_last.b64 %0, 1.0;" : "=l"(p));
    return p;
}
__device__ __forceinline__ void red_add_v2_el(float* p, float a, float b, uint64_t pol) {
    asm volatile("red.global.add.L2::cache_hint.v2.f32 [%0], {%1, %2}, %3;"
                 :: "l"(p), "f"(a), "f"(b), "l"(pol) : "memory");
}
__device__ __forceinline__ void red_add_v4_el(float* p, float a, float b, float c,
                                              float d, uint64_t pol) {
    asm volatile("red.global.add.L2::cache_hint.v4.f32 [%0], {%1, %2, %3, %4}, %5;"
                 :: "l"(p), "f"(a), "f"(b), "f"(c), "f"(d), "l"(pol) : "memory");
}
__device__ __forceinline__ void st_v4_el(float4* p, float4 v, uint64_t pol) {
    asm volatile("st.global.L2::cache_hint.v4.f32 [%0], {%1, %2, %3, %4}, %5;"
                 :: "l"(p), "f"(v.x), "f"(v.y), "f"(v.z), "f"(v.w), "l"(pol) : "memory");
}
__device__ __forceinline__ float2 ld_v2_el(const float2* p, uint64_t pol) {
    float2 r;
    asm volatile("ld.global.L2::cache_hint.v2.f32 {%0, %1}, [%2], %3;"
                 : "=f"(r.x), "=f"(r.y) : "l"(p), "l"(pol));
    return r;
}
__device__ __forceinline__ float4 ld_v4_el(const float4* p, uint64_t pol) {
    float4 r;
    asm volatile("ld.global.L2::cache_hint.v4.f32 {%0, %1, %2, %3}, [%4], %5;"
                 : "=f"(r.x), "=f"(r.y), "=f"(r.z), "=f"(r.w) : "l"(p), "l"(pol));
    return r;
}

// ---------------------------------------------------------------------------
// Kernel 1: zero the var-belief accumulator region, pinned evict_last.
// Primary for phaseA (PDL).
// ---------------------------------------------------------------------------
__global__ void __launch_bounds__(256) k_zero_var(float4* __restrict__ out, int n4) {
    cudaTriggerProgrammaticLaunchCompletion();
    int i = blockIdx.x * blockDim.x + threadIdx.x;
    if (i < n4) {
        uint64_t pol = mk_evict_last();
        st_v4_el(out + i, make_float4(0.f, 0.f, 0.f, 0.f), pol);
    }
}

// ---------------------------------------------------------------------------
// Kernel 2 (phase A, fused): block-partitioned independent work.
//   [0, B_acc):       var segment-sum (2 edges/thread, v2 red, evict_last)
//   [B_acc, +B_pot):  potentials -> factor output region copy (evict_last st)
// PDL secondary of k_zero_var; primary for k_var_mask.
// ---------------------------------------------------------------------------
__global__ void __launch_bounds__(256) k_phaseA(
        const float* __restrict__ msg,
        const int* __restrict__ var_idx,
        float* __restrict__ out_var, int E,
        const float4* __restrict__ pot4,
        float4* __restrict__ out_factor4, int F4,
        int B_acc) {
    cudaTriggerProgrammaticLaunchCompletion();
    int b = blockIdx.x;
    int tid = threadIdx.x;

    if (b < B_acc) {
        uint64_t pol = mk_evict_last();
        int i = b * 256 + tid;
        int e0 = 2 * i;
        if (e0 + 1 < E) {
            float4 m = __ldcs((const float4*)msg + i);
            int2 vv = __ldcs((const int2*)var_idx + i);
            cudaGridDependencySynchronize();            // out_var must be zeroed
            red_add_v2_el(out_var + 2 * vv.x, m.x, m.y, pol);
            red_add_v2_el(out_var + 2 * vv.y, m.z, m.w, pol);
        } else if (e0 < E) {
            float2 m = __ldcs((const float2*)msg + e0);
            int v = __ldcs(var_idx + e0);
            cudaGridDependencySynchronize();
            red_add_v2_el(out_var + 2 * v, m.x, m.y, pol);
        } else {
            cudaGridDependencySynchronize();
        }
    } else {
        // pot copy fully overwrites its range — independent of the zero kernel.
        uint64_t pol = mk_evict_last();
        int i = (b - B_acc) * 256 + tid;
        int j0 = 2 * i;
        if (j0 + 1 < F4) {
            st_v4_el(out_factor4 + j0,     __ldcs(pot4 + j0), pol);
            st_v4_el(out_factor4 + j0 + 1, __ldcs(pot4 + j0 + 1), pol);
        } else if (j0 < F4) {
            st_v4_el(out_factor4 + j0, __ldcs(pot4 + j0), pol);
        }
    }
}

// ---------------------------------------------------------------------------
// Kernel 3: var mask + clamp in place (evict_last ld/st — gathered next).
// PDL secondary of phaseA; primary for factor_accum.
// ---------------------------------------------------------------------------
__global__ void __launch_bounds__(256) k_var_mask(float4* __restrict__ var,
                                                  const int4* __restrict__ mask,
                                                  int nPairs) {
    cudaTriggerProgrammaticLaunchCompletion();
    int i = blockIdx.x * blockDim.x + threadIdx.x;
    if (i >= nPairs) {
        cudaGridDependencySynchronize();
        return;
    }
    uint64_t pol = mk_evict_last();
    int4 m = __ldcs(mask + i);              // independent stream — preamble
    cudaGridDependencySynchronize();        // wait for phaseA's REDs
    float4 v = ld_v4_el(var + i, pol);
    v.x = m.x ? LN_ZERO : fmaxf(v.x, LN_ZERO);
    v.y = m.y ? LN_ZERO : fmaxf(v.y, LN_ZERO);
    v.z = m.z ? LN_ZERO : fmaxf(v.z, LN_ZERO);
    v.w = m.w ? LN_ZERO : fmaxf(v.w, LN_ZERO);
    st_v4_el(var + i, v, pol);
}

// ---------------------------------------------------------------------------
// Kernel 4: per edge: v2f = vb[var] - msg, mask+clamp, permute (sidx element 1,
// bit 1), v4 red (evict_last) into factor accumulator. 2 edges per thread,
// T=512 (fewer CTAs per SM -> less cross-CTA L1tex-queue contention for the
// front-batched load burst; per-thread work identical to the verified best).
// PDL secondary of var_mask; primary for factor_mask.
// ---------------------------------------------------------------------------
__global__ void __launch_bounds__(512) k_factor_accum(
        const float4* __restrict__ msg2,
        const int2* __restrict__ fac_idx2,
        const int2* __restrict__ var_idx2,
        const int4* __restrict__ v2f_mask2,
        const int* __restrict__ sidx,
        const float2* __restrict__ var_beliefs,
        const float2* __restrict__ msg,
        const int* __restrict__ fac_idx,
        const int* __restrict__ var_idx,
        const int2* __restrict__ v2f_mask,
        float* __restrict__ out_factor, int E) {
    cudaTriggerProgrammaticLaunchCompletion();
    int i = blockIdx.x * blockDim.x + threadIdx.x;
    int e0 = 2 * i;
    if (e0 + 1 < E) {
        uint64_t pol = mk_evict_last();
        float4 m  = __ldcs(msg2 + i);
        int2   ff = __ldcs(fac_idx2 + i);
        int2   vv = __ldcs(var_idx2 + i);
        int4   mk = __ldcs(v2f_mask2 + i);
        int    s0 = __ldcs(sidx + 8 * i + 1);
        int    s1 = __ldcs(sidx + 8 * i + 5);
        cudaGridDependencySynchronize();    // var_beliefs final; out_factor potted
        float2 vb0 = ld_v2_el(var_beliefs + vv.x, pol);
        float2 vb1 = ld_v2_el(var_beliefs + vv.y, pol);

        float a = mk.x ? LN_ZERO : fmaxf(vb0.x - m.x, LN_ZERO);
        float b = mk.y ? LN_ZERO : fmaxf(vb0.y - m.y, LN_ZERO);
        bool p0 = (s0 & 2) != 0;
        red_add_v4_el(out_factor + 4 * ff.x, a, p0 ? b : a, p0 ? a : b, b, pol);

        float c = mk.z ? LN_ZERO : fmaxf(vb1.x - m.z, LN_ZERO);
        float d = mk.w ? LN_ZERO : fmaxf(vb1.y - m.w, LN_ZERO);
        bool p1 = (s1 & 2) != 0;
        red_add_v4_el(out_factor + 4 * ff.y, c, p1 ? d : c, p1 ? c : d, d, pol);
    } else if (e0 < E) {
        uint64_t pol = mk_evict_last();
        float2 m  = __ldcs(msg + e0);
        int    f  = __ldcs(fac_idx + e0);
        int    v  = __ldcs(var_idx + e0);
        int2   mk = __ldcs(v2f_mask + e0);
        int    s  = __ldcs(sidx + 4 * e0 + 1);
        cudaGridDependencySynchronize();
        float2 vb = ld_v2_el(var_beliefs + v, pol);
        float a = mk.x ? LN_ZERO : fmaxf(vb.x - m.x, LN_ZERO);
        float b = mk.y ? LN_ZERO : fmaxf(vb.y - m.y, LN_ZERO);
        bool p = (s & 2) != 0;
        red_add_v4_el(out_factor + 4 * f, a, p ? b : a, p ? a : b, b, pol);
    } else {
        cudaGridDependencySynchronize();
    }
}

// ---------------------------------------------------------------------------
// Kernel 5: factor mask + clamp in place, 2 factors per thread.
// PDL secondary of factor_accum.
// ---------------------------------------------------------------------------
__global__ void __launch_bounds__(256) k_factor_mask(float4* __restrict__ fb,
                                                     const int4* __restrict__ mask,
                                                     int nF) {
    int i = blockIdx.x * blockDim.x + threadIdx.x;
    int j0 = 2 * i;
    if (j0 + 1 < nF) {
        int4 m0 = __ldcs(mask + j0);
        int4 m1 = __ldcs(mask + j0 + 1);
        cudaGridDependencySynchronize();    // all REDs into out_factor done
        float4 v0 = fb[j0];
        float4 v1 = fb[j0 + 1];
        v0.x = m0.x ? LN_ZERO : fmaxf(v0.x, LN_ZERO);
        v0.y = m0.y ? LN_ZERO : fmaxf(v0.y, LN_ZERO);
        v0.z = m0.z ? LN_ZERO : fmaxf(v0.z, LN_ZERO);
        v0.w = m0.w ? LN_ZERO : fmaxf(v0.w, LN_ZERO);
        v1.x = m1.x ? LN_ZERO : fmaxf(v1.x, LN_ZERO);
        v1.y = m1.y ? LN_ZERO : fmaxf(v1.y, LN_ZERO);
        v1.z = m1.z ? LN_ZERO : fmaxf(v1.z, LN_ZERO);
        v1.w = m1.w ? LN_ZERO : fmaxf(v1.w, LN_ZERO);
        __stcs(fb + j0, v0);
        __stcs(fb + j0 + 1, v1);
    } else if (j0 < nF) {
        int4 m0 = __ldcs(mask + j0);
        cudaGridDependencySynchronize();
        float4 v0 = fb[j0];
        v0.x = m0.x ? LN_ZERO : fmaxf(v0.x, LN_ZERO);
        v0.y = m0.y ? LN_ZERO : fmaxf(v0.y, LN_ZERO);
        v0.z = m0.z ? LN_ZERO : fmaxf(v0.z, LN_ZERO);
        v0.w = m0.w ? LN_ZERO : fmaxf(v0.w, LN_ZERO);
        __stcs(fb + j0, v0);
    } else {
        cudaGridDependencySynchronize();
    }
}

// ---------------------------------------------------------------------------
// Host: launch chain with Programmatic Dependent Launch on each dependent
// kernel so successor CTAs launch during the predecessor's last wave.
// ---------------------------------------------------------------------------
template <typename... Args>
static void launch_pdl(void (*kern)(Args...), int grid, int block, Args... args) {
    cudaLaunchConfig_t cfg = {};
    cfg.gridDim = dim3((unsigned)grid, 1, 1);
    cfg.blockDim = dim3((unsigned)block, 1, 1);
    cfg.dynamicSmemBytes = 0;
    cfg.stream = 0;
    cudaLaunchAttribute attr[1];
    attr[0].id = cudaLaunchAttributeProgrammaticStreamSerialization;
    attr[0].val.programmaticStreamSerializationAllowed = 1;
    cfg.attrs = attr;
    cfg.numAttrs = 1;
    cudaLaunchKernelEx(&cfg, kern, args...);
}

extern "C" void kernel_launch(void* const* d_in, const int* in_sizes, int n_in,
                              void* d_out, int out_size) {
    const float* msg      = (const float*)d_in[0];
    const float* pot      = (const float*)d_in[1];
    const int*   edge_idx = (const int*)d_in[2];
    const int*   fp_mask  = (const int*)d_in[3];
    const int*   v2f_mask = (const int*)d_in[4];
    const int*   vb_mask  = (const int*)d_in[5];
    const int*   sidx     = (const int*)d_in[6];

    const int E = in_sizes[0] / 2;
    const int F = in_sizes[1] / 4;
    const int V = in_sizes[5] / 2;

    const int* fac_idx = edge_idx;
    const int* var_idx = edge_idx + E;

    float* out_var    = (float*)d_out;            // [V,2]
    float* out_factor = out_var + (size_t)2 * V;  // [F,2,2]

    const int T = 256;

    // 1) zero var accumulator region (pinned) — plain launch
    int nv4 = (2 * V) / 4;
    k_zero_var<<<(nv4 + T - 1) / T, T>>>((float4*)d_out, nv4);

    // 2) phase A: var segment-sum + potentials copy (fused) — PDL after zero
    int nPairsE = (E + 1) / 2;
    int B_acc  = (nPairsE + T - 1) / T;
    int nPotTh = (F + 1) / 2;
    int B_pot  = (nPotTh + T - 1) / T;
    launch_pdl(k_phaseA, B_acc + B_pot, T,
               msg, var_idx, out_var, E,
               (const float4*)pot, (float4*)out_factor, F, B_acc);

    // 3) var mask + clamp — PDL after phaseA
    int nPairsV = V / 2;
    launch_pdl(k_var_mask, (nPairsV + T - 1) / T, T,
               (float4*)out_var, (const int4*)vb_mask, nPairsV);

    // 4) edge pass: v2f + permute + factor segment-sum — PDL after var_mask
    //    T=512 experiment (same 2 edges/thread).
    launch_pdl(k_factor_accum, (nPairsE + 511) / 512, 512,
               (const float4*)msg, (const int2*)fac_idx, (const int2*)var_idx,
               (const int4*)v2f_mask, sidx, (const float2*)out_var,
               (const float2*)msg, fac_idx, var_idx, (const int2*)v2f_mask,
               out_factor, E);

    // 5) factor mask + clamp — PDL after factor_accum
    int nPairsF = (F + 1) / 2;
    launch_pdl(k_factor_mask, (nPairsF + T - 1) / T, T,
               (float4*)out_factor, (const int4*)fp_mask, F);
}